// round 13
// baseline (speedup 1.0000x reference)
#include <cuda_runtime.h>
#include <cstdint>

#define NB 8192
#define ND 512
#define NLAB 128
#define MARGIN 0.3f
#define INF_BITS 0x7f800000u
#define MAXG2 128

// ---------------- device scratch (no allocation allowed) ----------------
__device__ float         g_fnf[NB * ND];    // normalized features fp32 (16 MB)
__device__ float         g_fT[ND * NB];     // transposed (k-major) copy (16 MB)
__device__ float         g_sq[NB];          // sum of squares of normalized row
__device__ int           g_lab[NB];         // labels as int32
__device__ float         g_mp[NB];          // mean positive distance
__device__ float         g_mp2[NB];         // mean_pos^2
__device__ int           g_cnt[NB];         // positive count (incl self)
__device__ unsigned int  g_mind2[NB];       // running min d2 (float bits)
__device__ int           g_gidx[NLAB * MAXG2];  // per-label member indices
__device__ int           g_gcnt[NLAB];          // per-label member count

// ---------------- helpers ----------------
__device__ __forceinline__ float warp_sum(float v) {
    #pragma unroll
    for (int o = 16; o > 0; o >>= 1) v += __shfl_xor_sync(0xffffffffu, v, o);
    return v;
}
__device__ __forceinline__ void cp16(void* dst, const void* src) {
    unsigned d = (unsigned)__cvta_generic_to_shared(dst);
    asm volatile("cp.async.cg.shared.global [%0], [%1], 16;\n" :: "r"(d), "l"(src));
}
__device__ __forceinline__ void cp_commit() {
    asm volatile("cp.async.commit_group;\n");
}
template <int N>
__device__ __forceinline__ void cp_wait() {
    asm volatile("cp.async.wait_group %0;\n" :: "n"(N));
}

// ---------------- K1: normalize rows (fp32) ----------------
__global__ void k1_normalize(const float* __restrict__ x,
                             const long long* __restrict__ lab64) {
    int r = blockIdx.x;
    int tid = threadIdx.x;            // 128 threads
    __shared__ float red[4];

    float v[4];
    #pragma unroll
    for (int i = 0; i < 4; i++) v[i] = x[(size_t)r * ND + tid + i * 128];

    float s = v[0]*v[0] + v[1]*v[1] + v[2]*v[2] + v[3]*v[3];
    s = warp_sum(s);
    if ((tid & 31) == 0) red[tid >> 5] = s;
    __syncthreads();
    float tot = red[0] + red[1] + red[2] + red[3];
    float inv = 1.0f / fmaxf(sqrtf(tot), 1e-12f);

    float s2 = 0.f;
    #pragma unroll
    for (int i = 0; i < 4; i++) {
        float f = v[i] * inv;
        g_fnf[(size_t)r * ND + tid + i * 128] = f;
        s2 += f * f;
    }
    __syncthreads();
    s2 = warp_sum(s2);
    if ((tid & 31) == 0) red[tid >> 5] = s2;
    __syncthreads();
    if (tid == 0) {
        g_sq[r] = red[0] + red[1] + red[2] + red[3];
        g_lab[r] = (int)lab64[r];
        g_mind2[r] = INF_BITS;        // reset every launch (graph replay safe)
    }
}

// ---------------- K1b: transpose + per-label compaction ----------------
__global__ void k1b_transpose_scan() {
    __shared__ float t[32][33];
    __shared__ int s_scan[256];
    int x = threadIdx.x, y = threadIdx.y;
    int tid = y * 32 + x;

    if (blockIdx.y < 16) {
        int bx = blockIdx.x * 32;
        int by = blockIdx.y * 32;
        #pragma unroll
        for (int r = 0; r < 4; r++)
            t[y + r * 8][x] = g_fnf[(size_t)(bx + y + r * 8) * ND + by + x];
        __syncthreads();
        #pragma unroll
        for (int r = 0; r < 4; r++)
            g_fT[(size_t)(by + y + r * 8) * NB + bx + x] = t[x][y + r * 8];
    } else {
        int L = blockIdx.x;
        if (L >= NLAB) return;
        int c = 0;
        for (int j = tid; j < NB; j += 256) c += (g_lab[j] == L);
        s_scan[tid] = c;
        __syncthreads();
        #pragma unroll
        for (int off = 1; off < 256; off <<= 1) {
            int v = 0;
            if (tid >= off) v = s_scan[tid - off];
            __syncthreads();
            s_scan[tid] += v;
            __syncthreads();
        }
        int total = s_scan[255];
        int cnt = total < MAXG2 ? total : MAXG2;
        int pos = s_scan[tid] - c;
        for (int j = tid; j < NB; j += 256) {
            if (g_lab[j] == L) { if (pos < MAXG2) g_gidx[L * MAXG2 + pos] = j; pos++; }
        }
        if (tid == 0) g_gcnt[L] = cnt;
    }
}

// ---------------- K2: per-label mean positive distance (GEMM) --------------
#define BKC 32
__global__ __launch_bounds__(256) void k2_gemm() {
    __shared__ int s_idx[MAXG2];
    __shared__ __align__(16) float SA[BKC][34];
    __shared__ __align__(16) float SB[BKC][68];
    __shared__ float s_part[16][32];

    int L = blockIdx.x;
    int cnt = g_gcnt[L];
    int i0 = blockIdx.y * 32;
    if (i0 >= cnt) return;

    int tid = threadIdx.x;
    int ty = tid >> 4, tx = tid & 15;

    if (tid < MAXG2) s_idx[tid] = (tid < cnt) ? g_gidx[L * MAXG2 + tid] : g_gidx[L * MAXG2];
    __syncthreads();

    float rsum[2] = {0.f, 0.f};

    int sar = tid & 31, sak = tid >> 5;
    int sbc = tid & 63, sbk = tid >> 6;
    int gaR = i0 + sar;  if (gaR >= cnt) gaR = 0;
    const float* pA = g_fnf + (size_t)s_idx[gaR] * ND;

    for (int j0 = 0; j0 < cnt; j0 += 64) {
        float acc[2][4];
        #pragma unroll
        for (int i = 0; i < 2; i++)
            #pragma unroll
            for (int j = 0; j < 4; j++) acc[i][j] = 0.f;

        int gbC = j0 + sbc; if (gbC >= cnt) gbC = 0;
        const float* pB = g_fnf + (size_t)s_idx[gbC] * ND;

        for (int kb = 0; kb < ND; kb += BKC) {
            __syncthreads();
            {
                float4 v = *(const float4*)(pA + kb + sak * 4);
                SA[sak*4+0][sar] = v.x; SA[sak*4+1][sar] = v.y;
                SA[sak*4+2][sar] = v.z; SA[sak*4+3][sar] = v.w;
                float4 w0 = *(const float4*)(pB + kb + sbk * 8);
                float4 w1 = *(const float4*)(pB + kb + sbk * 8 + 4);
                SB[sbk*8+0][sbc] = w0.x; SB[sbk*8+1][sbc] = w0.y;
                SB[sbk*8+2][sbc] = w0.z; SB[sbk*8+3][sbc] = w0.w;
                SB[sbk*8+4][sbc] = w1.x; SB[sbk*8+5][sbc] = w1.y;
                SB[sbk*8+6][sbc] = w1.z; SB[sbk*8+7][sbc] = w1.w;
            }
            __syncthreads();
            #pragma unroll
            for (int k = 0; k < BKC; k++) {
                float2 a2 = *(const float2*)&SA[k][ty * 2];
                float4 b4 = *(const float4*)&SB[k][tx * 4];
                acc[0][0] = fmaf(a2.x, b4.x, acc[0][0]);
                acc[0][1] = fmaf(a2.x, b4.y, acc[0][1]);
                acc[0][2] = fmaf(a2.x, b4.z, acc[0][2]);
                acc[0][3] = fmaf(a2.x, b4.w, acc[0][3]);
                acc[1][0] = fmaf(a2.y, b4.x, acc[1][0]);
                acc[1][1] = fmaf(a2.y, b4.y, acc[1][1]);
                acc[1][2] = fmaf(a2.y, b4.z, acc[1][2]);
                acc[1][3] = fmaf(a2.y, b4.w, acc[1][3]);
            }
        }
        #pragma unroll
        for (int i = 0; i < 2; i++) {
            int gi = i0 + ty * 2 + i;
            if (gi < cnt) {
                int ia = s_idx[gi];
                float sqa = g_sq[ia];
                #pragma unroll
                for (int j = 0; j < 4; j++) {
                    int gj = j0 + tx * 4 + j;
                    if (gj < cnt) {
                        int ib = s_idx[gj];
                        if (ib != ia) {
                            float d2 = fmaxf(sqa + g_sq[ib] - 2.f * acc[i][j], 0.f);
                            if (d2 > 0.f) rsum[i] += sqrtf(d2);
                        }
                    }
                }
            }
        }
    }
    __syncthreads();
    s_part[tx][ty * 2 + 0] = rsum[0];
    s_part[tx][ty * 2 + 1] = rsum[1];
    __syncthreads();
    if (tid < 32 && i0 + tid < cnt) {
        float s = 0.f;
        #pragma unroll
        for (int x2 = 0; x2 < 16; x2++) s += s_part[x2][tid];
        int a = s_idx[i0 + tid];
        float mp = s / (float)cnt;
        g_mp[a] = mp;
        g_mp2[a] = mp * mp;
        g_cnt[a] = cnt;
    }
}

// ---------------- K3: fp32 FFMA Gram, 256x128 tile, 16x8/thread ------------
// cp.async smem staging + explicit fragment double-buffering to cover the
// 29-cyc LDS latency at 8 warps/SM.
#define AS_OFF   0                        // 2*16*260 = 8320
#define BS_OFF   8320                     // 2*16*132 = 4224
#define CMIN_OFF 12544                    // 16*128  = 2048
#define SQI_OFF  14592                    // 256
#define MPI_OFF  14848                    // 256
#define LABI_OFF 15104                    // 256 (int)
#define SQJ_OFF  15360                    // 128
#define MPJ_OFF  15488                    // 128
#define LABJ_OFF 15616                    // 128 (int)
#define K3_SMEM_FLOATS 15744
#define K3_SMEM_BYTES (K3_SMEM_FLOATS * 4)

extern __shared__ float k3sm[];

__global__ __launch_bounds__(256) void k3_gram() {
    // linear block id -> (bi over 256-row tiles, bj over 128-col tiles), bj>=2bi
    int rem = blockIdx.x, bi = 0;
    while (rem >= 64 - 2 * bi) { rem -= 64 - 2 * bi; bi++; }
    int bj = 2 * bi + rem;

    float* As = k3sm + AS_OFF;            // [2][16][260]
    float* Bs = k3sm + BS_OFF;            // [2][16][132]
    float* s_cmin = k3sm + CMIN_OFF;      // [16][128]
    float* s_sqi = k3sm + SQI_OFF;
    float* s_mp2i = k3sm + MPI_OFF;
    int*   s_labi = (int*)(k3sm + LABI_OFF);
    float* s_sqj = k3sm + SQJ_OFF;
    float* s_mp2j = k3sm + MPJ_OFF;
    int*   s_labj = (int*)(k3sm + LABJ_OFF);

    int tid = threadIdx.x;
    int ty = tid >> 4, tx = tid & 15;
    int rowBase = bi * 256, colBase = bj * 128;

    {
        s_sqi[tid]  = g_sq[rowBase + tid];
        s_mp2i[tid] = g_mp2[rowBase + tid];
        s_labi[tid] = g_lab[rowBase + tid];
        if (tid < 128) {
            s_sqj[tid]  = g_sq[colBase + tid];
            s_mp2j[tid] = g_mp2[colBase + tid];
            s_labj[tid] = g_lab[colBase + tid];
        }
    }

    int kk_ = tid >> 4;                   // k within tile (0..15)
    int sg  = tid & 15;                   // segment
    const float* pTa = g_fT + (size_t)kk_ * NB + rowBase + sg * 4;
    const float* pTb = g_fT + (size_t)kk_ * NB + colBase + sg * 4;
    const size_t kstep = (size_t)16 * NB;

    float acc[16][8];
    #pragma unroll
    for (int i = 0; i < 16; i++)
        #pragma unroll
        for (int j = 0; j < 8; j++) acc[i][j] = 0.f;

    // prologue: stage kt=0 into buffer 0 via cp.async
    #pragma unroll
    for (int q = 0; q < 4; q++)
        cp16(&As[(0 * 16 + kk_) * 260 + sg * 4 + q * 64], pTa + q * 64);
    #pragma unroll
    for (int q = 0; q < 2; q++)
        cp16(&Bs[(0 * 16 + kk_) * 132 + sg * 4 + q * 64], pTb + q * 64);
    cp_commit();
    cp_wait<0>();
    __syncthreads();

    for (int kt = 0; kt < 32; kt++) {
        int cur = kt & 1, nxt = cur ^ 1;
        if (kt < 31) {
            size_t ko = (size_t)(kt + 1) * kstep;
            #pragma unroll
            for (int q = 0; q < 4; q++)
                cp16(&As[(nxt * 16 + kk_) * 260 + sg * 4 + q * 64], pTa + ko + q * 64);
            #pragma unroll
            for (int q = 0; q < 2; q++)
                cp16(&Bs[(nxt * 16 + kk_) * 132 + sg * 4 + q * 64], pTb + ko + q * 64);
            cp_commit();
        }
        #pragma unroll 1
        for (int kh = 0; kh < 2; kh++) {
            float a[2][16], b[2][8];
            {   // preload first k of this half
                const float* Ak = &As[(cur * 16 + kh * 8) * 260 + ty * 16];
                const float* Bk = &Bs[(cur * 16 + kh * 8) * 132 + tx * 8];
                float4 A0 = *(const float4*)(Ak);
                float4 A1 = *(const float4*)(Ak + 4);
                float4 A2 = *(const float4*)(Ak + 8);
                float4 A3 = *(const float4*)(Ak + 12);
                float4 B0 = *(const float4*)(Bk);
                float4 B1 = *(const float4*)(Bk + 4);
                a[0][0]=A0.x; a[0][1]=A0.y; a[0][2]=A0.z; a[0][3]=A0.w;
                a[0][4]=A1.x; a[0][5]=A1.y; a[0][6]=A1.z; a[0][7]=A1.w;
                a[0][8]=A2.x; a[0][9]=A2.y; a[0][10]=A2.z; a[0][11]=A2.w;
                a[0][12]=A3.x; a[0][13]=A3.y; a[0][14]=A3.z; a[0][15]=A3.w;
                b[0][0]=B0.x; b[0][1]=B0.y; b[0][2]=B0.z; b[0][3]=B0.w;
                b[0][4]=B1.x; b[0][5]=B1.y; b[0][6]=B1.z; b[0][7]=B1.w;
            }
            #pragma unroll
            for (int k2i = 0; k2i < 8; k2i++) {
                int cb = k2i & 1, nb = cb ^ 1;
                if (k2i < 7) {
                    const float* Ak = &As[(cur * 16 + kh * 8 + k2i + 1) * 260 + ty * 16];
                    const float* Bk = &Bs[(cur * 16 + kh * 8 + k2i + 1) * 132 + tx * 8];
                    float4 A0 = *(const float4*)(Ak);
                    float4 A1 = *(const float4*)(Ak + 4);
                    float4 A2 = *(const float4*)(Ak + 8);
                    float4 A3 = *(const float4*)(Ak + 12);
                    float4 B0 = *(const float4*)(Bk);
                    float4 B1 = *(const float4*)(Bk + 4);
                    a[nb][0]=A0.x; a[nb][1]=A0.y; a[nb][2]=A0.z; a[nb][3]=A0.w;
                    a[nb][4]=A1.x; a[nb][5]=A1.y; a[nb][6]=A1.z; a[nb][7]=A1.w;
                    a[nb][8]=A2.x; a[nb][9]=A2.y; a[nb][10]=A2.z; a[nb][11]=A2.w;
                    a[nb][12]=A3.x; a[nb][13]=A3.y; a[nb][14]=A3.z; a[nb][15]=A3.w;
                    b[nb][0]=B0.x; b[nb][1]=B0.y; b[nb][2]=B0.z; b[nb][3]=B0.w;
                    b[nb][4]=B1.x; b[nb][5]=B1.y; b[nb][6]=B1.z; b[nb][7]=B1.w;
                }
                #pragma unroll
                for (int i = 0; i < 16; i++)
                    #pragma unroll
                    for (int j = 0; j < 8; j++)
                        acc[i][j] = fmaf(a[cb][i], b[cb][j], acc[i][j]);
            }
        }
        if (kt < 31) {
            cp_wait<0>();
            __syncthreads();
        }
    }

    // ---------------- fused epilogue ----------------
    float rmin[16], cmin[8];
    #pragma unroll
    for (int i = 0; i < 16; i++) rmin[i] = __uint_as_float(INF_BITS);
    #pragma unroll
    for (int j = 0; j < 8; j++)  cmin[j] = __uint_as_float(INF_BITS);

    #pragma unroll
    for (int i = 0; i < 16; i++) {
        int rr = ty * 16 + i;
        float sqr = s_sqi[rr], mpr = s_mp2i[rr];
        int labr = s_labi[rr];
        #pragma unroll
        for (int j = 0; j < 8; j++) {
            int cc = tx * 8 + j;
            float d2 = fmaxf(sqr + s_sqj[cc] - 2.f * acc[i][j], 0.f);
            bool diff = (s_labj[cc] != labr);
            if (diff && d2 > mpr)        rmin[i] = fminf(rmin[i], d2);
            if (diff && d2 > s_mp2j[cc]) cmin[j] = fminf(cmin[j], d2);
        }
    }

    // row-side: reduce across the 16 tx lanes (xor stays within half-warp)
    #pragma unroll
    for (int i = 0; i < 16; i++) {
        float v = rmin[i];
        #pragma unroll
        for (int o = 1; o < 16; o <<= 1)
            v = fminf(v, __shfl_xor_sync(0xffffffffu, v, o));
        if (tx == 0)
            atomicMin(&g_mind2[rowBase + ty * 16 + i], __float_as_uint(v));
    }

    // col-side: stage per-ty partials, reduce by 128 threads
    __syncthreads();
    #pragma unroll
    for (int j = 0; j < 8; j++) s_cmin[ty * 128 + tx * 8 + j] = cmin[j];
    __syncthreads();
    if (tid < 128) {
        float m = __uint_as_float(INF_BITS);
        #pragma unroll
        for (int t2 = 0; t2 < 16; t2++) m = fminf(m, s_cmin[t2 * 128 + tid]);
        atomicMin(&g_mind2[colBase + tid], __float_as_uint(m));
    }
}

// ---------------- K4: final reduction ----------------
__global__ void k4_finalize(float* __restrict__ out) {
    __shared__ float ssum[32];
    __shared__ int   scnt[32];
    int tid = threadIdx.x;            // 1024 threads
    float s = 0.f; int c = 0;
    for (int i = tid; i < NB; i += 1024) {
        int pc = g_cnt[i];
        unsigned u = g_mind2[i];
        if (pc > 1 && pc < NB && u < INF_BITS) {
            float md = sqrtf(__uint_as_float(u));
            float per = g_mp[i] - md + MARGIN;
            if (per > 0.f) s += per;
            c++;
        }
    }
    s = warp_sum(s);
    #pragma unroll
    for (int o = 16; o > 0; o >>= 1) c += __shfl_xor_sync(0xffffffffu, c, o);
    if ((tid & 31) == 0) { ssum[tid >> 5] = s; scnt[tid >> 5] = c; }
    __syncthreads();
    if (tid < 32) {
        float s2 = ssum[tid]; int c2 = scnt[tid];
        s2 = warp_sum(s2);
        #pragma unroll
        for (int o = 16; o > 0; o >>= 1) c2 += __shfl_xor_sync(0xffffffffu, c2, o);
        if (tid == 0) out[0] = (c2 > 0) ? s2 / (float)c2 : 0.f;
    }
}

// ---------------- launch ----------------
extern "C" void kernel_launch(void* const* d_in, const int* in_sizes, int n_in,
                              void* d_out, int out_size) {
    const float* features = (const float*)d_in[0];
    const long long* labels = (const long long*)d_in[1];
    float* out = (float*)d_out;

    cudaFuncSetAttribute(k3_gram,
                         cudaFuncAttributeMaxDynamicSharedMemorySize, K3_SMEM_BYTES);

    k1_normalize<<<NB, 128>>>(features, labels);            // my 1st
    k1b_transpose_scan<<<dim3(256, 17), dim3(32, 8)>>>();   // my 2nd
    k2_gemm<<<dim3(NLAB, 4), 256>>>();                      // my 3rd
    k3_gram<<<1056, 256, K3_SMEM_BYTES>>>();                // my 4th <- PROFILED
    k4_finalize<<<1, 1024>>>(out);
}

// round 14
// speedup vs baseline: 1.0156x; 1.0156x over previous
#include <cuda_runtime.h>
#include <cstdint>

#define NB 8192
#define ND 512
#define NLAB 128
#define MARGIN 0.3f
#define INF_BITS 0x7f800000u
#define MAXG2 128

// ---------------- device scratch (no allocation allowed) ----------------
__device__ float         g_fnf[NB * ND];    // normalized features fp32 (16 MB)
__device__ float         g_fT[ND * NB];     // transposed (k-major) copy (16 MB)
__device__ float         g_sq[NB];          // sum of squares of normalized row
__device__ int           g_lab[NB];         // labels as int32
__device__ float         g_mp[NB];          // mean positive distance
__device__ float         g_mp2[NB];         // mean_pos^2
__device__ int           g_cnt[NB];         // positive count (incl self)
__device__ unsigned int  g_mind2[NB];       // running min d2 (float bits)
__device__ int           g_gidx[NLAB * MAXG2];  // per-label member indices
__device__ int           g_gcnt[NLAB];          // per-label member count

// ---------------- helpers ----------------
__device__ __forceinline__ float warp_sum(float v) {
    #pragma unroll
    for (int o = 16; o > 0; o >>= 1) v += __shfl_xor_sync(0xffffffffu, v, o);
    return v;
}

// ---------------- K1: normalize rows (fp32) ----------------
__global__ void k1_normalize(const float* __restrict__ x,
                             const long long* __restrict__ lab64) {
    int r = blockIdx.x;
    int tid = threadIdx.x;            // 128 threads
    __shared__ float red[4];

    float v[4];
    #pragma unroll
    for (int i = 0; i < 4; i++) v[i] = x[(size_t)r * ND + tid + i * 128];

    float s = v[0]*v[0] + v[1]*v[1] + v[2]*v[2] + v[3]*v[3];
    s = warp_sum(s);
    if ((tid & 31) == 0) red[tid >> 5] = s;
    __syncthreads();
    float tot = red[0] + red[1] + red[2] + red[3];
    float inv = 1.0f / fmaxf(sqrtf(tot), 1e-12f);

    float s2 = 0.f;
    #pragma unroll
    for (int i = 0; i < 4; i++) {
        float f = v[i] * inv;
        g_fnf[(size_t)r * ND + tid + i * 128] = f;
        s2 += f * f;
    }
    __syncthreads();
    s2 = warp_sum(s2);
    if ((tid & 31) == 0) red[tid >> 5] = s2;
    __syncthreads();
    if (tid == 0) {
        g_sq[r] = red[0] + red[1] + red[2] + red[3];
        g_lab[r] = (int)lab64[r];
        g_mind2[r] = INF_BITS;        // reset every launch (graph replay safe)
    }
}

// ---------------- K1b: transpose + per-label compaction ----------------
__global__ void k1b_transpose_scan() {
    __shared__ float t[32][33];
    __shared__ int s_scan[256];
    int x = threadIdx.x, y = threadIdx.y;
    int tid = y * 32 + x;

    if (blockIdx.y < 16) {
        int bx = blockIdx.x * 32;
        int by = blockIdx.y * 32;
        #pragma unroll
        for (int r = 0; r < 4; r++)
            t[y + r * 8][x] = g_fnf[(size_t)(bx + y + r * 8) * ND + by + x];
        __syncthreads();
        #pragma unroll
        for (int r = 0; r < 4; r++)
            g_fT[(size_t)(by + y + r * 8) * NB + bx + x] = t[x][y + r * 8];
    } else {
        int L = blockIdx.x;
        if (L >= NLAB) return;
        int c = 0;
        for (int j = tid; j < NB; j += 256) c += (g_lab[j] == L);
        s_scan[tid] = c;
        __syncthreads();
        #pragma unroll
        for (int off = 1; off < 256; off <<= 1) {
            int v = 0;
            if (tid >= off) v = s_scan[tid - off];
            __syncthreads();
            s_scan[tid] += v;
            __syncthreads();
        }
        int total = s_scan[255];
        int cnt = total < MAXG2 ? total : MAXG2;
        int pos = s_scan[tid] - c;
        for (int j = tid; j < NB; j += 256) {
            if (g_lab[j] == L) { if (pos < MAXG2) g_gidx[L * MAXG2 + pos] = j; pos++; }
        }
        if (tid == 0) g_gcnt[L] = cnt;
    }
}

// ---------------- K2: per-label mean positive distance (GEMM) --------------
#define BKC 32
__global__ __launch_bounds__(256) void k2_gemm() {
    __shared__ int s_idx[MAXG2];
    __shared__ __align__(16) float SA[BKC][34];
    __shared__ __align__(16) float SB[BKC][68];
    __shared__ float s_part[16][32];

    int L = blockIdx.x;
    int cnt = g_gcnt[L];
    int i0 = blockIdx.y * 32;
    if (i0 >= cnt) return;

    int tid = threadIdx.x;
    int ty = tid >> 4, tx = tid & 15;

    if (tid < MAXG2) s_idx[tid] = (tid < cnt) ? g_gidx[L * MAXG2 + tid] : g_gidx[L * MAXG2];
    __syncthreads();

    float rsum[2] = {0.f, 0.f};

    int sar = tid & 31, sak = tid >> 5;
    int sbc = tid & 63, sbk = tid >> 6;
    int gaR = i0 + sar;  if (gaR >= cnt) gaR = 0;
    const float* pA = g_fnf + (size_t)s_idx[gaR] * ND;

    for (int j0 = 0; j0 < cnt; j0 += 64) {
        float acc[2][4];
        #pragma unroll
        for (int i = 0; i < 2; i++)
            #pragma unroll
            for (int j = 0; j < 4; j++) acc[i][j] = 0.f;

        int gbC = j0 + sbc; if (gbC >= cnt) gbC = 0;
        const float* pB = g_fnf + (size_t)s_idx[gbC] * ND;

        for (int kb = 0; kb < ND; kb += BKC) {
            __syncthreads();
            {
                float4 v = *(const float4*)(pA + kb + sak * 4);
                SA[sak*4+0][sar] = v.x; SA[sak*4+1][sar] = v.y;
                SA[sak*4+2][sar] = v.z; SA[sak*4+3][sar] = v.w;
                float4 w0 = *(const float4*)(pB + kb + sbk * 8);
                float4 w1 = *(const float4*)(pB + kb + sbk * 8 + 4);
                SB[sbk*8+0][sbc] = w0.x; SB[sbk*8+1][sbc] = w0.y;
                SB[sbk*8+2][sbc] = w0.z; SB[sbk*8+3][sbc] = w0.w;
                SB[sbk*8+4][sbc] = w1.x; SB[sbk*8+5][sbc] = w1.y;
                SB[sbk*8+6][sbc] = w1.z; SB[sbk*8+7][sbc] = w1.w;
            }
            __syncthreads();
            #pragma unroll
            for (int k = 0; k < BKC; k++) {
                float2 a2 = *(const float2*)&SA[k][ty * 2];
                float4 b4 = *(const float4*)&SB[k][tx * 4];
                acc[0][0] = fmaf(a2.x, b4.x, acc[0][0]);
                acc[0][1] = fmaf(a2.x, b4.y, acc[0][1]);
                acc[0][2] = fmaf(a2.x, b4.z, acc[0][2]);
                acc[0][3] = fmaf(a2.x, b4.w, acc[0][3]);
                acc[1][0] = fmaf(a2.y, b4.x, acc[1][0]);
                acc[1][1] = fmaf(a2.y, b4.y, acc[1][1]);
                acc[1][2] = fmaf(a2.y, b4.z, acc[1][2]);
                acc[1][3] = fmaf(a2.y, b4.w, acc[1][3]);
            }
        }
        #pragma unroll
        for (int i = 0; i < 2; i++) {
            int gi = i0 + ty * 2 + i;
            if (gi < cnt) {
                int ia = s_idx[gi];
                float sqa = g_sq[ia];
                #pragma unroll
                for (int j = 0; j < 4; j++) {
                    int gj = j0 + tx * 4 + j;
                    if (gj < cnt) {
                        int ib = s_idx[gj];
                        if (ib != ia) {
                            float d2 = fmaxf(sqa + g_sq[ib] - 2.f * acc[i][j], 0.f);
                            if (d2 > 0.f) rsum[i] += sqrtf(d2);
                        }
                    }
                }
            }
        }
    }
    __syncthreads();
    s_part[tx][ty * 2 + 0] = rsum[0];
    s_part[tx][ty * 2 + 1] = rsum[1];
    __syncthreads();
    if (tid < 32 && i0 + tid < cnt) {
        float s = 0.f;
        #pragma unroll
        for (int x2 = 0; x2 < 16; x2++) s += s_part[x2][tid];
        int a = s_idx[i0 + tid];
        float mp = s / (float)cnt;
        g_mp[a] = mp;
        g_mp2[a] = mp * mp;
        g_cnt[a] = cnt;
    }
}

// ---------------- K3: fp32 FFMA Gram, 256x128 tile, 16x8/thread ------------
// R12 configuration (measured best, 664us) with inner loop consuming float4
// components directly (no scalar temp arrays).
#define AS_OFF   0                        // 2*16*260 = 8320
#define BS_OFF   8320                     // 2*16*132 = 4224
#define CMIN_OFF 12544                    // 16*128  = 2048
#define SQI_OFF  14592                    // 256
#define MPI_OFF  14848                    // 256
#define LABI_OFF 15104                    // 256 (int)
#define SQJ_OFF  15360                    // 128
#define MPJ_OFF  15488                    // 128
#define LABJ_OFF 15616                    // 128 (int)
#define K3_SMEM_FLOATS 15744
#define K3_SMEM_BYTES (K3_SMEM_FLOATS * 4)

extern __shared__ float k3sm[];

__global__ __launch_bounds__(256) void k3_gram() {
    // linear block id -> (bi over 256-row tiles, bj over 128-col tiles), bj>=2bi
    int rem = blockIdx.x, bi = 0;
    while (rem >= 64 - 2 * bi) { rem -= 64 - 2 * bi; bi++; }
    int bj = 2 * bi + rem;

    float* As = k3sm + AS_OFF;            // [2][16][260]
    float* Bs = k3sm + BS_OFF;            // [2][16][132]
    float* s_cmin = k3sm + CMIN_OFF;      // [16][128]
    float* s_sqi = k3sm + SQI_OFF;
    float* s_mp2i = k3sm + MPI_OFF;
    int*   s_labi = (int*)(k3sm + LABI_OFF);
    float* s_sqj = k3sm + SQJ_OFF;
    float* s_mp2j = k3sm + MPJ_OFF;
    int*   s_labj = (int*)(k3sm + LABJ_OFF);

    int tid = threadIdx.x;
    int ty = tid >> 4, tx = tid & 15;
    int rowBase = bi * 256, colBase = bj * 128;

    {
        s_sqi[tid]  = g_sq[rowBase + tid];
        s_mp2i[tid] = g_mp2[rowBase + tid];
        s_labi[tid] = g_lab[rowBase + tid];
        if (tid < 128) {
            s_sqj[tid]  = g_sq[colBase + tid];
            s_mp2j[tid] = g_mp2[colBase + tid];
            s_labj[tid] = g_lab[colBase + tid];
        }
    }

    int kk_ = tid >> 4;                   // k within tile (0..15)
    int sg  = tid & 15;                   // segment
    const float* pTa = g_fT + (size_t)kk_ * NB + rowBase + sg * 4;
    const float* pTb = g_fT + (size_t)kk_ * NB + colBase + sg * 4;
    const size_t kstep = (size_t)16 * NB;

    float acc[16][8];
    #pragma unroll
    for (int i = 0; i < 16; i++)
        #pragma unroll
        for (int j = 0; j < 8; j++) acc[i][j] = 0.f;

    float4 ar[4], br[2];
    #pragma unroll
    for (int q = 0; q < 4; q++) ar[q] = *(const float4*)(pTa + q * 64);
    #pragma unroll
    for (int q = 0; q < 2; q++) br[q] = *(const float4*)(pTb + q * 64);
    #pragma unroll
    for (int q = 0; q < 4; q++)
        *(float4*)&As[(0 * 16 + kk_) * 260 + sg * 4 + q * 64] = ar[q];
    #pragma unroll
    for (int q = 0; q < 2; q++)
        *(float4*)&Bs[(0 * 16 + kk_) * 132 + sg * 4 + q * 64] = br[q];
    __syncthreads();

    for (int kt = 0; kt < 32; kt++) {
        int cur = kt & 1, nxt = cur ^ 1;
        if (kt < 31) {
            size_t ko = (size_t)(kt + 1) * kstep;
            #pragma unroll
            for (int q = 0; q < 4; q++) ar[q] = *(const float4*)(pTa + ko + q * 64);
            #pragma unroll
            for (int q = 0; q < 2; q++) br[q] = *(const float4*)(pTb + ko + q * 64);
        }
        #pragma unroll 1
        for (int kh = 0; kh < 2; kh++) {
            #pragma unroll
            for (int k2i = 0; k2i < 8; k2i++) {
                int k = kh * 8 + k2i;
                const float* Ak = &As[(cur * 16 + k) * 260 + ty * 16];
                const float* Bk = &Bs[(cur * 16 + k) * 132 + tx * 8];
                float4 A0 = *(const float4*)(Ak);
                float4 A1 = *(const float4*)(Ak + 4);
                float4 A2 = *(const float4*)(Ak + 8);
                float4 A3 = *(const float4*)(Ak + 12);
                float4 B0 = *(const float4*)(Bk);
                float4 B1 = *(const float4*)(Bk + 4);
                #pragma unroll
                for (int j = 0; j < 4; j++) {
                    float bj0 = j == 0 ? B0.x : (j == 1 ? B0.y : (j == 2 ? B0.z : B0.w));
                    acc[0][j]  = fmaf(A0.x, bj0, acc[0][j]);
                    acc[1][j]  = fmaf(A0.y, bj0, acc[1][j]);
                    acc[2][j]  = fmaf(A0.z, bj0, acc[2][j]);
                    acc[3][j]  = fmaf(A0.w, bj0, acc[3][j]);
                    acc[4][j]  = fmaf(A1.x, bj0, acc[4][j]);
                    acc[5][j]  = fmaf(A1.y, bj0, acc[5][j]);
                    acc[6][j]  = fmaf(A1.z, bj0, acc[6][j]);
                    acc[7][j]  = fmaf(A1.w, bj0, acc[7][j]);
                    acc[8][j]  = fmaf(A2.x, bj0, acc[8][j]);
                    acc[9][j]  = fmaf(A2.y, bj0, acc[9][j]);
                    acc[10][j] = fmaf(A2.z, bj0, acc[10][j]);
                    acc[11][j] = fmaf(A2.w, bj0, acc[11][j]);
                    acc[12][j] = fmaf(A3.x, bj0, acc[12][j]);
                    acc[13][j] = fmaf(A3.y, bj0, acc[13][j]);
                    acc[14][j] = fmaf(A3.z, bj0, acc[14][j]);
                    acc[15][j] = fmaf(A3.w, bj0, acc[15][j]);
                }
                #pragma unroll
                for (int j = 0; j < 4; j++) {
                    float bj1 = j == 0 ? B1.x : (j == 1 ? B1.y : (j == 2 ? B1.z : B1.w));
                    acc[0][4+j]  = fmaf(A0.x, bj1, acc[0][4+j]);
                    acc[1][4+j]  = fmaf(A0.y, bj1, acc[1][4+j]);
                    acc[2][4+j]  = fmaf(A0.z, bj1, acc[2][4+j]);
                    acc[3][4+j]  = fmaf(A0.w, bj1, acc[3][4+j]);
                    acc[4][4+j]  = fmaf(A1.x, bj1, acc[4][4+j]);
                    acc[5][4+j]  = fmaf(A1.y, bj1, acc[5][4+j]);
                    acc[6][4+j]  = fmaf(A1.z, bj1, acc[6][4+j]);
                    acc[7][4+j]  = fmaf(A1.w, bj1, acc[7][4+j]);
                    acc[8][4+j]  = fmaf(A2.x, bj1, acc[8][4+j]);
                    acc[9][4+j]  = fmaf(A2.y, bj1, acc[9][4+j]);
                    acc[10][4+j] = fmaf(A2.z, bj1, acc[10][4+j]);
                    acc[11][4+j] = fmaf(A2.w, bj1, acc[11][4+j]);
                    acc[12][4+j] = fmaf(A3.x, bj1, acc[12][4+j]);
                    acc[13][4+j] = fmaf(A3.y, bj1, acc[13][4+j]);
                    acc[14][4+j] = fmaf(A3.z, bj1, acc[14][4+j]);
                    acc[15][4+j] = fmaf(A3.w, bj1, acc[15][4+j]);
                }
            }
        }
        if (kt < 31) {
            #pragma unroll
            for (int q = 0; q < 4; q++)
                *(float4*)&As[(nxt * 16 + kk_) * 260 + sg * 4 + q * 64] = ar[q];
            #pragma unroll
            for (int q = 0; q < 2; q++)
                *(float4*)&Bs[(nxt * 16 + kk_) * 132 + sg * 4 + q * 64] = br[q];
        }
        __syncthreads();
    }

    // ---------------- fused epilogue ----------------
    float rmin[16], cmin[8];
    #pragma unroll
    for (int i = 0; i < 16; i++) rmin[i] = __uint_as_float(INF_BITS);
    #pragma unroll
    for (int j = 0; j < 8; j++)  cmin[j] = __uint_as_float(INF_BITS);

    #pragma unroll
    for (int i = 0; i < 16; i++) {
        int rr = ty * 16 + i;
        float sqr = s_sqi[rr], mpr = s_mp2i[rr];
        int labr = s_labi[rr];
        #pragma unroll
        for (int j = 0; j < 8; j++) {
            int cc = tx * 8 + j;
            float d2 = fmaxf(sqr + s_sqj[cc] - 2.f * acc[i][j], 0.f);
            bool diff = (s_labj[cc] != labr);
            if (diff && d2 > mpr)        rmin[i] = fminf(rmin[i], d2);
            if (diff && d2 > s_mp2j[cc]) cmin[j] = fminf(cmin[j], d2);
        }
    }

    // row-side: reduce across the 16 tx lanes (xor stays within half-warp)
    #pragma unroll
    for (int i = 0; i < 16; i++) {
        float v = rmin[i];
        #pragma unroll
        for (int o = 1; o < 16; o <<= 1)
            v = fminf(v, __shfl_xor_sync(0xffffffffu, v, o));
        if (tx == 0)
            atomicMin(&g_mind2[rowBase + ty * 16 + i], __float_as_uint(v));
    }

    // col-side: stage per-ty partials, reduce by 128 threads
    #pragma unroll
    for (int j = 0; j < 8; j++) s_cmin[ty * 128 + tx * 8 + j] = cmin[j];
    __syncthreads();
    if (tid < 128) {
        float m = __uint_as_float(INF_BITS);
        #pragma unroll
        for (int t2 = 0; t2 < 16; t2++) m = fminf(m, s_cmin[t2 * 128 + tid]);
        atomicMin(&g_mind2[colBase + tid], __float_as_uint(m));
    }
}

// ---------------- K4: final reduction ----------------
__global__ void k4_finalize(float* __restrict__ out) {
    __shared__ float ssum[32];
    __shared__ int   scnt[32];
    int tid = threadIdx.x;            // 1024 threads
    float s = 0.f; int c = 0;
    for (int i = tid; i < NB; i += 1024) {
        int pc = g_cnt[i];
        unsigned u = g_mind2[i];
        if (pc > 1 && pc < NB && u < INF_BITS) {
            float md = sqrtf(__uint_as_float(u));
            float per = g_mp[i] - md + MARGIN;
            if (per > 0.f) s += per;
            c++;
        }
    }
    s = warp_sum(s);
    #pragma unroll
    for (int o = 16; o > 0; o >>= 1) c += __shfl_xor_sync(0xffffffffu, c, o);
    if ((tid & 31) == 0) { ssum[tid >> 5] = s; scnt[tid >> 5] = c; }
    __syncthreads();
    if (tid < 32) {
        float s2 = ssum[tid]; int c2 = scnt[tid];
        s2 = warp_sum(s2);
        #pragma unroll
        for (int o = 16; o > 0; o >>= 1) c2 += __shfl_xor_sync(0xffffffffu, c2, o);
        if (tid == 0) out[0] = (c2 > 0) ? s2 / (float)c2 : 0.f;
    }
}

// ---------------- launch ----------------
extern "C" void kernel_launch(void* const* d_in, const int* in_sizes, int n_in,
                              void* d_out, int out_size) {
    const float* features = (const float*)d_in[0];
    const long long* labels = (const long long*)d_in[1];
    float* out = (float*)d_out;

    cudaFuncSetAttribute(k3_gram,
                         cudaFuncAttributeMaxDynamicSharedMemorySize, K3_SMEM_BYTES);

    k1_normalize<<<NB, 128>>>(features, labels);            // my 1st
    k1b_transpose_scan<<<dim3(256, 17), dim3(32, 8)>>>();   // my 2nd
    k2_gemm<<<dim3(NLAB, 4), 256>>>();                      // my 3rd
    k3_gram<<<1056, 256, K3_SMEM_BYTES>>>();                // my 4th <- PROFILED
    k4_finalize<<<1, 1024>>>(out);
}

// round 15
// speedup vs baseline: 1.0470x; 1.0309x over previous
#include <cuda_runtime.h>
#include <cstdint>

#define NB 8192
#define ND 512
#define NLAB 128
#define MARGIN 0.3f
#define INF_BITS 0x7f800000u
#define MAXG2 128

// ---------------- device scratch (no allocation allowed) ----------------
__device__ float         g_fnf[NB * ND];    // normalized features fp32 (16 MB)
__device__ float         g_fT[ND * NB];     // transposed (k-major) copy (16 MB)
__device__ float         g_sq[NB];          // sum of squares of normalized row
__device__ int           g_lab[NB];         // labels as int32
__device__ float         g_mp[NB];          // mean positive distance
__device__ float         g_mp2[NB];         // mean_pos^2
__device__ int           g_cnt[NB];         // positive count (incl self)
__device__ unsigned int  g_mind2[NB];       // running min d2 (float bits)
__device__ int           g_gidx[NLAB * MAXG2];  // per-label member indices
__device__ int           g_gcnt[NLAB];          // per-label member count

// ---------------- helpers ----------------
__device__ __forceinline__ float warp_sum(float v) {
    #pragma unroll
    for (int o = 16; o > 0; o >>= 1) v += __shfl_xor_sync(0xffffffffu, v, o);
    return v;
}

// ---------------- K1: normalize rows (fp32) ----------------
__global__ void k1_normalize(const float* __restrict__ x,
                             const long long* __restrict__ lab64) {
    int r = blockIdx.x;
    int tid = threadIdx.x;            // 128 threads
    __shared__ float red[4];

    float v[4];
    #pragma unroll
    for (int i = 0; i < 4; i++) v[i] = x[(size_t)r * ND + tid + i * 128];

    float s = v[0]*v[0] + v[1]*v[1] + v[2]*v[2] + v[3]*v[3];
    s = warp_sum(s);
    if ((tid & 31) == 0) red[tid >> 5] = s;
    __syncthreads();
    float tot = red[0] + red[1] + red[2] + red[3];
    float inv = 1.0f / fmaxf(sqrtf(tot), 1e-12f);

    float s2 = 0.f;
    #pragma unroll
    for (int i = 0; i < 4; i++) {
        float f = v[i] * inv;
        g_fnf[(size_t)r * ND + tid + i * 128] = f;
        s2 += f * f;
    }
    __syncthreads();
    s2 = warp_sum(s2);
    if ((tid & 31) == 0) red[tid >> 5] = s2;
    __syncthreads();
    if (tid == 0) {
        g_sq[r] = red[0] + red[1] + red[2] + red[3];
        g_lab[r] = (int)lab64[r];
        g_mind2[r] = INF_BITS;        // reset every launch (graph replay safe)
    }
}

// ---------------- K1b: transpose + per-label compaction ----------------
__global__ void k1b_transpose_scan() {
    __shared__ float t[32][33];
    __shared__ int s_scan[256];
    int x = threadIdx.x, y = threadIdx.y;
    int tid = y * 32 + x;

    if (blockIdx.y < 16) {
        int bx = blockIdx.x * 32;
        int by = blockIdx.y * 32;
        #pragma unroll
        for (int r = 0; r < 4; r++)
            t[y + r * 8][x] = g_fnf[(size_t)(bx + y + r * 8) * ND + by + x];
        __syncthreads();
        #pragma unroll
        for (int r = 0; r < 4; r++)
            g_fT[(size_t)(by + y + r * 8) * NB + bx + x] = t[x][y + r * 8];
    } else {
        int L = blockIdx.x;
        if (L >= NLAB) return;
        int c = 0;
        for (int j = tid; j < NB; j += 256) c += (g_lab[j] == L);
        s_scan[tid] = c;
        __syncthreads();
        #pragma unroll
        for (int off = 1; off < 256; off <<= 1) {
            int v = 0;
            if (tid >= off) v = s_scan[tid - off];
            __syncthreads();
            s_scan[tid] += v;
            __syncthreads();
        }
        int total = s_scan[255];
        int cnt = total < MAXG2 ? total : MAXG2;
        int pos = s_scan[tid] - c;
        for (int j = tid; j < NB; j += 256) {
            if (g_lab[j] == L) { if (pos < MAXG2) g_gidx[L * MAXG2 + pos] = j; pos++; }
        }
        if (tid == 0) g_gcnt[L] = cnt;
    }
}

// ---------------- K2: per-label mean positive distance (GEMM) --------------
#define BKC 32
__global__ __launch_bounds__(256) void k2_gemm() {
    __shared__ int s_idx[MAXG2];
    __shared__ __align__(16) float SA[BKC][34];
    __shared__ __align__(16) float SB[BKC][68];
    __shared__ float s_part[16][32];

    int L = blockIdx.x;
    int cnt = g_gcnt[L];
    int i0 = blockIdx.y * 32;
    if (i0 >= cnt) return;

    int tid = threadIdx.x;
    int ty = tid >> 4, tx = tid & 15;

    if (tid < MAXG2) s_idx[tid] = (tid < cnt) ? g_gidx[L * MAXG2 + tid] : g_gidx[L * MAXG2];
    __syncthreads();

    float rsum[2] = {0.f, 0.f};

    int sar = tid & 31, sak = tid >> 5;
    int sbc = tid & 63, sbk = tid >> 6;
    int gaR = i0 + sar;  if (gaR >= cnt) gaR = 0;
    const float* pA = g_fnf + (size_t)s_idx[gaR] * ND;

    for (int j0 = 0; j0 < cnt; j0 += 64) {
        float acc[2][4];
        #pragma unroll
        for (int i = 0; i < 2; i++)
            #pragma unroll
            for (int j = 0; j < 4; j++) acc[i][j] = 0.f;

        int gbC = j0 + sbc; if (gbC >= cnt) gbC = 0;
        const float* pB = g_fnf + (size_t)s_idx[gbC] * ND;

        for (int kb = 0; kb < ND; kb += BKC) {
            __syncthreads();
            {
                float4 v = *(const float4*)(pA + kb + sak * 4);
                SA[sak*4+0][sar] = v.x; SA[sak*4+1][sar] = v.y;
                SA[sak*4+2][sar] = v.z; SA[sak*4+3][sar] = v.w;
                float4 w0 = *(const float4*)(pB + kb + sbk * 8);
                float4 w1 = *(const float4*)(pB + kb + sbk * 8 + 4);
                SB[sbk*8+0][sbc] = w0.x; SB[sbk*8+1][sbc] = w0.y;
                SB[sbk*8+2][sbc] = w0.z; SB[sbk*8+3][sbc] = w0.w;
                SB[sbk*8+4][sbc] = w1.x; SB[sbk*8+5][sbc] = w1.y;
                SB[sbk*8+6][sbc] = w1.z; SB[sbk*8+7][sbc] = w1.w;
            }
            __syncthreads();
            #pragma unroll
            for (int k = 0; k < BKC; k++) {
                float2 a2 = *(const float2*)&SA[k][ty * 2];
                float4 b4 = *(const float4*)&SB[k][tx * 4];
                acc[0][0] = fmaf(a2.x, b4.x, acc[0][0]);
                acc[0][1] = fmaf(a2.x, b4.y, acc[0][1]);
                acc[0][2] = fmaf(a2.x, b4.z, acc[0][2]);
                acc[0][3] = fmaf(a2.x, b4.w, acc[0][3]);
                acc[1][0] = fmaf(a2.y, b4.x, acc[1][0]);
                acc[1][1] = fmaf(a2.y, b4.y, acc[1][1]);
                acc[1][2] = fmaf(a2.y, b4.z, acc[1][2]);
                acc[1][3] = fmaf(a2.y, b4.w, acc[1][3]);
            }
        }
        #pragma unroll
        for (int i = 0; i < 2; i++) {
            int gi = i0 + ty * 2 + i;
            if (gi < cnt) {
                int ia = s_idx[gi];
                float sqa = g_sq[ia];
                #pragma unroll
                for (int j = 0; j < 4; j++) {
                    int gj = j0 + tx * 4 + j;
                    if (gj < cnt) {
                        int ib = s_idx[gj];
                        if (ib != ia) {
                            float d2 = fmaxf(sqa + g_sq[ib] - 2.f * acc[i][j], 0.f);
                            if (d2 > 0.f) rsum[i] += sqrtf(d2);
                        }
                    }
                }
            }
        }
    }
    __syncthreads();
    s_part[tx][ty * 2 + 0] = rsum[0];
    s_part[tx][ty * 2 + 1] = rsum[1];
    __syncthreads();
    if (tid < 32 && i0 + tid < cnt) {
        float s = 0.f;
        #pragma unroll
        for (int x2 = 0; x2 < 16; x2++) s += s_part[x2][tid];
        int a = s_idx[i0 + tid];
        float mp = s / (float)cnt;
        g_mp[a] = mp;
        g_mp2[a] = mp * mp;
        g_cnt[a] = cnt;
    }
}

// ---------------- K3: fp32 FFMA Gram, 256x128 tile, 16x8/thread, BK=32 -----
// R12 inner loop (measured best) with half the kt-boundary count.
#define KB3 32
#define AS_OFF   0                        // 2*32*260 = 16640
#define BS_OFF   16640                    // 2*32*132 = 8448
#define CMIN_OFF 25088                    // 16*128 = 2048
#define SQI_OFF  27136                    // 256
#define MPI_OFF  27392                    // 256
#define LABI_OFF 27648                    // 256 (int)
#define SQJ_OFF  27904                    // 128
#define MPJ_OFF  28032                    // 128
#define LABJ_OFF 28160                    // 128 (int)
#define K3_SMEM_FLOATS 28288
#define K3_SMEM_BYTES (K3_SMEM_FLOATS * 4)

extern __shared__ float k3sm[];

__global__ __launch_bounds__(256) void k3_gram() {
    // linear block id -> (bi over 256-row tiles, bj over 128-col tiles), bj>=2bi
    int rem = blockIdx.x, bi = 0;
    while (rem >= 64 - 2 * bi) { rem -= 64 - 2 * bi; bi++; }
    int bj = 2 * bi + rem;

    float* As = k3sm + AS_OFF;            // [2][32][260]
    float* Bs = k3sm + BS_OFF;            // [2][32][132]
    float* s_cmin = k3sm + CMIN_OFF;      // [16][128]
    float* s_sqi = k3sm + SQI_OFF;
    float* s_mp2i = k3sm + MPI_OFF;
    int*   s_labi = (int*)(k3sm + LABI_OFF);
    float* s_sqj = k3sm + SQJ_OFF;
    float* s_mp2j = k3sm + MPJ_OFF;
    int*   s_labj = (int*)(k3sm + LABJ_OFF);

    int tid = threadIdx.x;
    int ty = tid >> 4, tx = tid & 15;
    int rowBase = bi * 256, colBase = bj * 128;

    {
        s_sqi[tid]  = g_sq[rowBase + tid];
        s_mp2i[tid] = g_mp2[rowBase + tid];
        s_labi[tid] = g_lab[rowBase + tid];
        if (tid < 128) {
            s_sqj[tid]  = g_sq[colBase + tid];
            s_mp2j[tid] = g_mp2[colBase + tid];
            s_labj[tid] = g_lab[colBase + tid];
        }
    }

    // staging: kk2 = k-row (0..31), sg2 = segment (0..7)
    int kk2 = tid >> 3;
    int sg2 = tid & 7;
    const float* pTa = g_fT + (size_t)kk2 * NB + rowBase + sg2 * 4;
    const float* pTb = g_fT + (size_t)kk2 * NB + colBase + sg2 * 4;
    const size_t kstep = (size_t)KB3 * NB;

    float acc[16][8];
    #pragma unroll
    for (int i = 0; i < 16; i++)
        #pragma unroll
        for (int j = 0; j < 8; j++) acc[i][j] = 0.f;

    float4 ar[8], br[4];
    #pragma unroll
    for (int q = 0; q < 8; q++) ar[q] = *(const float4*)(pTa + q * 32);
    #pragma unroll
    for (int q = 0; q < 4; q++) br[q] = *(const float4*)(pTb + q * 32);
    #pragma unroll
    for (int q = 0; q < 8; q++)
        *(float4*)&As[(0 * KB3 + kk2) * 260 + sg2 * 4 + q * 32] = ar[q];
    #pragma unroll
    for (int q = 0; q < 4; q++)
        *(float4*)&Bs[(0 * KB3 + kk2) * 132 + sg2 * 4 + q * 32] = br[q];
    __syncthreads();

    for (int kt = 0; kt < 16; kt++) {
        int cur = kt & 1, nxt = cur ^ 1;
        if (kt < 15) {
            size_t ko = (size_t)(kt + 1) * kstep;
            #pragma unroll
            for (int q = 0; q < 8; q++) ar[q] = *(const float4*)(pTa + ko + q * 32);
            #pragma unroll
            for (int q = 0; q < 4; q++) br[q] = *(const float4*)(pTb + ko + q * 32);
        }
        #pragma unroll 1
        for (int kh = 0; kh < 4; kh++) {
            #pragma unroll
            for (int k2i = 0; k2i < 8; k2i++) {
                int k = kh * 8 + k2i;
                const float* Ak = &As[(cur * KB3 + k) * 260 + ty * 16];
                const float* Bk = &Bs[(cur * KB3 + k) * 132 + tx * 8];
                float a[16], b[8];
                float4 A0 = *(const float4*)(Ak);
                float4 A1 = *(const float4*)(Ak + 4);
                float4 A2 = *(const float4*)(Ak + 8);
                float4 A3 = *(const float4*)(Ak + 12);
                float4 B0 = *(const float4*)(Bk);
                float4 B1 = *(const float4*)(Bk + 4);
                a[0]=A0.x; a[1]=A0.y; a[2]=A0.z; a[3]=A0.w;
                a[4]=A1.x; a[5]=A1.y; a[6]=A1.z; a[7]=A1.w;
                a[8]=A2.x; a[9]=A2.y; a[10]=A2.z; a[11]=A2.w;
                a[12]=A3.x; a[13]=A3.y; a[14]=A3.z; a[15]=A3.w;
                b[0]=B0.x; b[1]=B0.y; b[2]=B0.z; b[3]=B0.w;
                b[4]=B1.x; b[5]=B1.y; b[6]=B1.z; b[7]=B1.w;
                #pragma unroll
                for (int i = 0; i < 16; i++)
                    #pragma unroll
                    for (int j = 0; j < 8; j++)
                        acc[i][j] = fmaf(a[i], b[j], acc[i][j]);
            }
        }
        if (kt < 15) {
            #pragma unroll
            for (int q = 0; q < 8; q++)
                *(float4*)&As[(nxt * KB3 + kk2) * 260 + sg2 * 4 + q * 32] = ar[q];
            #pragma unroll
            for (int q = 0; q < 4; q++)
                *(float4*)&Bs[(nxt * KB3 + kk2) * 132 + sg2 * 4 + q * 32] = br[q];
        }
        __syncthreads();
    }

    // ---------------- fused epilogue ----------------
    float rmin[16], cmin[8];
    #pragma unroll
    for (int i = 0; i < 16; i++) rmin[i] = __uint_as_float(INF_BITS);
    #pragma unroll
    for (int j = 0; j < 8; j++)  cmin[j] = __uint_as_float(INF_BITS);

    #pragma unroll
    for (int i = 0; i < 16; i++) {
        int rr = ty * 16 + i;
        float sqr = s_sqi[rr], mpr = s_mp2i[rr];
        int labr = s_labi[rr];
        #pragma unroll
        for (int j = 0; j < 8; j++) {
            int cc = tx * 8 + j;
            float d2 = fmaxf(sqr + s_sqj[cc] - 2.f * acc[i][j], 0.f);
            bool diff = (s_labj[cc] != labr);
            if (diff && d2 > mpr)        rmin[i] = fminf(rmin[i], d2);
            if (diff && d2 > s_mp2j[cc]) cmin[j] = fminf(cmin[j], d2);
        }
    }

    // row-side: reduce across the 16 tx lanes (xor stays within half-warp)
    #pragma unroll
    for (int i = 0; i < 16; i++) {
        float v = rmin[i];
        #pragma unroll
        for (int o = 1; o < 16; o <<= 1)
            v = fminf(v, __shfl_xor_sync(0xffffffffu, v, o));
        if (tx == 0)
            atomicMin(&g_mind2[rowBase + ty * 16 + i], __float_as_uint(v));
    }

    // col-side: stage per-ty partials, reduce by 128 threads
    #pragma unroll
    for (int j = 0; j < 8; j++) s_cmin[ty * 128 + tx * 8 + j] = cmin[j];
    __syncthreads();
    if (tid < 128) {
        float m = __uint_as_float(INF_BITS);
        #pragma unroll
        for (int t2 = 0; t2 < 16; t2++) m = fminf(m, s_cmin[t2 * 128 + tid]);
        atomicMin(&g_mind2[colBase + tid], __float_as_uint(m));
    }
}

// ---------------- K4: final reduction ----------------
__global__ void k4_finalize(float* __restrict__ out) {
    __shared__ float ssum[32];
    __shared__ int   scnt[32];
    int tid = threadIdx.x;            // 1024 threads
    float s = 0.f; int c = 0;
    for (int i = tid; i < NB; i += 1024) {
        int pc = g_cnt[i];
        unsigned u = g_mind2[i];
        if (pc > 1 && pc < NB && u < INF_BITS) {
            float md = sqrtf(__uint_as_float(u));
            float per = g_mp[i] - md + MARGIN;
            if (per > 0.f) s += per;
            c++;
        }
    }
    s = warp_sum(s);
    #pragma unroll
    for (int o = 16; o > 0; o >>= 1) c += __shfl_xor_sync(0xffffffffu, c, o);
    if ((tid & 31) == 0) { ssum[tid >> 5] = s; scnt[tid >> 5] = c; }
    __syncthreads();
    if (tid < 32) {
        float s2 = ssum[tid]; int c2 = scnt[tid];
        s2 = warp_sum(s2);
        #pragma unroll
        for (int o = 16; o > 0; o >>= 1) c2 += __shfl_xor_sync(0xffffffffu, c2, o);
        if (tid == 0) out[0] = (c2 > 0) ? s2 / (float)c2 : 0.f;
    }
}

// ---------------- launch ----------------
extern "C" void kernel_launch(void* const* d_in, const int* in_sizes, int n_in,
                              void* d_out, int out_size) {
    const float* features = (const float*)d_in[0];
    const long long* labels = (const long long*)d_in[1];
    float* out = (float*)d_out;

    cudaFuncSetAttribute(k3_gram,
                         cudaFuncAttributeMaxDynamicSharedMemorySize, K3_SMEM_BYTES);

    k1_normalize<<<NB, 128>>>(features, labels);            // my 1st
    k1b_transpose_scan<<<dim3(256, 17), dim3(32, 8)>>>();   // my 2nd
    k2_gemm<<<dim3(NLAB, 4), 256>>>();                      // my 3rd
    k3_gram<<<1056, 256, K3_SMEM_BYTES>>>();                // my 4th <- PROFILED
    k4_finalize<<<1, 1024>>>(out);
}